// round 8
// baseline (speedup 1.0000x reference)
#include <cuda_runtime.h>
#include <cstdint>

// Problem constants: coords in [0,256)^3, R=2 -> coarse coords in [0,128)^3.
// Coarse key = (bx<<14)|(by<<7)|bz  (21 bits). Numeric key order == lexicographic
// row order, which matches jnp.unique's sorted output.
static constexpr int NKEYS           = 1 << 21;                // 2,097,152
static constexpr int SCAN_BLK        = 256;
static constexpr int SCAN_ITEMS      = 8;                      // items per thread
static constexpr int SCAN_TILE       = SCAN_BLK * SCAN_ITEMS;  // 2048
static constexpr int NUM_SCAN_BLOCKS = NKEYS / SCAN_TILE;      // 1024
static constexpr int MAXN            = 524288;                 // >= 500,000 points

// Scratch (static __device__ globals — no allocation allowed)
__device__ unsigned int g_flag[NKEYS];            // 8 MB: key present?
__device__ unsigned int g_scan[NKEYS];            // 8 MB: intra-block exclusive scan
__device__ unsigned int g_bsum[NUM_SCAN_BLOCKS];  // per-block sums -> exclusive
__device__ int          g_winner[MAXN * 8];       // 16 MB: last-writer idx+1 per slot

// ---------------------------------------------------------------------------
// Zero g_flag + g_winner, and pre-fill out_coords with -1.0f (jnp.unique fill,
// emitted as float32 because the harness output buffer dtype is float32).
// k_emit later overwrites rows [0, num_unique).
__global__ void k_init(long long w4, float* __restrict__ out_coords, int n3) {
    long long i = (long long)blockIdx.x * blockDim.x + threadIdx.x;
    long long stride = (long long)gridDim.x * blockDim.x;
    uint4 z = make_uint4(0u, 0u, 0u, 0u);
    const long long f4 = NKEYS / 4;
    for (long long j = i; j < f4; j += stride)
        reinterpret_cast<uint4*>(g_flag)[j] = z;
    for (long long j = i; j < w4; j += stride)
        reinterpret_cast<uint4*>(g_winner)[j] = z;
    for (long long j = i; j < n3; j += stride)
        out_coords[j] = -1.0f;
}

// ---------------------------------------------------------------------------
// Mark present coarse keys
__global__ void k_mark(const int* __restrict__ coords, int n) {
    int i = blockIdx.x * blockDim.x + threadIdx.x;
    if (i >= n) return;
    int cx = coords[3 * i], cy = coords[3 * i + 1], cz = coords[3 * i + 2];
    unsigned key = ((unsigned)(cx >> 1) << 14) | ((unsigned)(cy >> 1) << 7)
                 | (unsigned)(cz >> 1);
    g_flag[key] = 1u;   // idempotent, no atomic needed
}

// ---------------------------------------------------------------------------
// Pass 1: per-block exclusive scan of flags (2048 items/block)
__global__ void k_scan1() {
    __shared__ unsigned sh[SCAN_BLK];
    int t = threadIdx.x;
    int base = blockIdx.x * SCAN_TILE + t * SCAN_ITEMS;
    uint4 a = *reinterpret_cast<const uint4*>(g_flag + base);
    uint4 b = *reinterpret_cast<const uint4*>(g_flag + base + 4);
    unsigned v[8] = {a.x, a.y, a.z, a.w, b.x, b.y, b.z, b.w};
    unsigned s = 0;
#pragma unroll
    for (int k = 0; k < 8; k++) s += v[k];
    sh[t] = s;
    __syncthreads();
    for (int off = 1; off < SCAN_BLK; off <<= 1) {
        unsigned x = (t >= off) ? sh[t - off] : 0u;
        __syncthreads();
        sh[t] += x;
        __syncthreads();
    }
    if (t == SCAN_BLK - 1) g_bsum[blockIdx.x] = sh[t];
    unsigned run = sh[t] - s;   // exclusive offset for this thread
    unsigned o[8];
#pragma unroll
    for (int k = 0; k < 8; k++) { o[k] = run; run += v[k]; }
    *reinterpret_cast<uint4*>(g_scan + base)     = make_uint4(o[0], o[1], o[2], o[3]);
    *reinterpret_cast<uint4*>(g_scan + base + 4) = make_uint4(o[4], o[5], o[6], o[7]);
}

// Pass 2: exclusive scan of the 1024 block sums (single block)
__global__ void k_scan2() {
    __shared__ unsigned sh[SCAN_BLK];
    int t = threadIdx.x;
    int base = t * 4;
    uint4 a = *reinterpret_cast<const uint4*>(g_bsum + base);
    unsigned v[4] = {a.x, a.y, a.z, a.w};
    unsigned s = v[0] + v[1] + v[2] + v[3];
    sh[t] = s;
    __syncthreads();
    for (int off = 1; off < SCAN_BLK; off <<= 1) {
        unsigned x = (t >= off) ? sh[t - off] : 0u;
        __syncthreads();
        sh[t] += x;
        __syncthreads();
    }
    unsigned run = sh[t] - s;
    unsigned o[4];
#pragma unroll
    for (int k = 0; k < 4; k++) { o[k] = run; run += v[k]; }
    *reinterpret_cast<uint4*>(g_bsum + base) = make_uint4(o[0], o[1], o[2], o[3]);
}

// ---------------------------------------------------------------------------
// Emit sorted unique coarse coords as float32 values
// (rows beyond num_unique stay -1.0f from k_init)
__global__ void k_emit(float* __restrict__ out_coords) {
    int key = blockIdx.x * blockDim.x + threadIdx.x;
    if (key >= NKEYS) return;
    if (!g_flag[key]) return;
    unsigned r = g_scan[key] + g_bsum[key >> 11];   // 2048 keys per scan block
    out_coords[3 * r]     = (float)(key >> 14);
    out_coords[3 * r + 1] = (float)((key >> 7) & 127);
    out_coords[3 * r + 2] = (float)(key & 127);
}

// ---------------------------------------------------------------------------
// Per point: record last-writer index per (row, slot).
// atomicMax(i+1) == "last index wins", matching XLA's sequential scatter order.
__global__ void k_winner(const int* __restrict__ coords, int n) {
    int i = blockIdx.x * blockDim.x + threadIdx.x;
    if (i >= n) return;
    int cx = coords[3 * i], cy = coords[3 * i + 1], cz = coords[3 * i + 2];
    unsigned key = ((unsigned)(cx >> 1) << 14) | ((unsigned)(cy >> 1) << 7)
                 | (unsigned)(cz >> 1);
    unsigned inv = g_scan[key] + g_bsum[key >> 11];
    unsigned off = ((unsigned)(cx & 1) << 2) | ((unsigned)(cy & 1) << 1)
                 | (unsigned)(cz & 1);
    atomicMax(&g_winner[inv * 8 + off], i + 1);
}

// ---------------------------------------------------------------------------
// Gather epilogue: one thread per (row, slot); writes agg exactly once.
// Empty slots -> zeros; occupied -> 16 channels of the winning point.
__global__ void k_gather(const float* __restrict__ feats,
                         float* __restrict__ agg, long long nslots) {
    long long s = (long long)blockIdx.x * blockDim.x + threadIdx.x;
    if (s >= nslots) return;
    int w = g_winner[s];
    float4* dst = reinterpret_cast<float4*>(agg + s * 16);
    if (w == 0) {
        float4 z = make_float4(0.f, 0.f, 0.f, 0.f);
        dst[0] = z; dst[1] = z; dst[2] = z; dst[3] = z;
    } else {
        const float4* src = reinterpret_cast<const float4*>(feats + (size_t)(w - 1) * 16);
        dst[0] = src[0];
        dst[1] = src[1];
        dst[2] = src[2];
        dst[3] = src[3];
    }
}

// ---------------------------------------------------------------------------
extern "C" void kernel_launch(void* const* d_in, const int* in_sizes, int n_in,
                              void* d_out, int out_size) {
    const float* feats  = (const float*)d_in[0];   // [n,16] f32
    const int*   coords = (const int*)d_in[1];     // [n,3]  i32
    const int n = in_sizes[0] / 16;

    // Output layout (all float32): unique_coords [n,3] then agg [n,128]
    float* out_coords = (float*)d_out;
    float* agg        = (float*)d_out + (size_t)n * 3;

    const int TB = 256;
    const int nb_pts = (n + TB - 1) / TB;

    // Zero scratch (flag 8MB + winner 16MB) and pre-fill out_coords with -1.0f
    long long w4 = (long long)n * 2;               // n*8 ints / 4
    k_init<<<1024, TB>>>(w4, out_coords, n * 3);

    // Unique via flag + prefix sum over 2^21 keys
    k_mark<<<nb_pts, TB>>>(coords, n);
    k_scan1<<<NUM_SCAN_BLOCKS, SCAN_BLK>>>();
    k_scan2<<<1, SCAN_BLK>>>();
    k_emit<<<NKEYS / TB, TB>>>(out_coords);

    // Deterministic last-wins winner per slot, then single-write gather epilogue
    k_winner<<<nb_pts, TB>>>(coords, n);
    long long nslots = (long long)n * 8;
    int nb_slots = (int)((nslots + TB - 1) / TB);
    k_gather<<<nb_slots, TB>>>(feats, agg, nslots);
}